// round 12
// baseline (speedup 1.0000x reference)
#include <cuda_runtime.h>
#include <math.h>

// Problem constants (fixed by reference setup_inputs)
#define BB 32
#define CC 16
#define HH 256
#define WW 256
#define HW (HH * WW)
#define N_OBJ 16
#define TPB 256
#define SEG 1024                        // pixels per segment (= TPB*4)
#define PXB (2 * SEG)                   // 2048 pixels per CTA (two adjacent slabs)
#define NBLOCKS_X (HW / PXB)            // 32
#define NBLOCKS   (NBLOCKS_X * BB)      // 1024

// Global accumulators (zero-initialized at module load; last block resets
// them after consuming, so every graph replay starts from zero).
__device__ double g_base_sum;
__device__ double g_spatial_sum;
__device__ unsigned int g_counts[BB];
__device__ unsigned int g_arrive;

// Fused kernel: each CTA covers 2048 consecutive pixels (two 1024-px segments)
// of one batch. Per-thread: 2 coalesced 4-px groups, 1024 px apart.
// grid: (32, 32) ; block: 256
__global__ void __launch_bounds__(TPB) scl_fused_kernel(
    const float* __restrict__ pred,
    const float* __restrict__ targ,
    const float* __restrict__ layout,
    const float* __restrict__ object_counts,
    float* __restrict__ out)
{
    const int b = blockIdx.y;
    const int tid = threadIdx.x;

    __shared__ int s_xs[N_OBJ], s_xe[N_OBJ], s_ys[N_OBJ], s_ye[N_OBJ];
    __shared__ int s_valid[N_OBJ];
    if (tid < N_OBJ) {
        const float* L = layout + ((size_t)b * N_OBJ + tid) * 4;
        float x = L[0], y = L[1], w = L[2], h = L[3];
        s_valid[tid] = (x > 0.0f) && (y > 0.0f);
        s_xs[tid] = (int)floorf(x * (float)WW);
        s_ys[tid] = (int)floorf(y * (float)HH);
        s_xe[tid] = (int)floorf((x + w) * (float)WW);
        s_ye[tid] = (int)floorf((y + h) * (float)HH);
    }
    __syncthreads();

    // Segment 0: pix0..pix0+3 ; Segment 1: pix0+SEG..pix0+SEG+3
    // Both perfectly coalesced per LDG.128 (thread-consecutive 4 px).
    const int pix0 = blockIdx.x * PXB + tid * 4;
    const int row0 = pix0 / WW;
    const int row1 = row0 + (SEG / WW);           // +4 rows
    const int col0 = pix0 % WW;                   // same for both segments

    const size_t base = (size_t)b * CC * HW + pix0;

    float ab[8];
    #pragma unroll
    for (int i = 0; i < 8; i++) ab[i] = 0.f;
    float sq = 0.f;

    #pragma unroll
    for (int c = 0; c < CC; c++) {
        const float* pp = pred + base + (size_t)c * HW;
        const float* tp = targ + base + (size_t)c * HW;
        const float4 p0 = __ldcs(reinterpret_cast<const float4*>(pp));
        const float4 p1 = __ldcs(reinterpret_cast<const float4*>(pp + SEG));
        const float4 t0 = __ldcs(reinterpret_cast<const float4*>(tp));
        const float4 t1 = __ldcs(reinterpret_cast<const float4*>(tp + SEG));

        float d0 = p0.x - t0.x, d1 = p0.y - t0.y, d2 = p0.z - t0.z, d3 = p0.w - t0.w;
        float d4 = p1.x - t1.x, d5 = p1.y - t1.y, d6 = p1.z - t1.z, d7 = p1.w - t1.w;
        sq = fmaf(d0, d0, sq); sq = fmaf(d1, d1, sq);
        sq = fmaf(d2, d2, sq); sq = fmaf(d3, d3, sq);
        sq = fmaf(d4, d4, sq); sq = fmaf(d5, d5, sq);
        sq = fmaf(d6, d6, sq); sq = fmaf(d7, d7, sq);

        ab[0] += fabsf(p0.x); ab[1] += fabsf(p0.y);
        ab[2] += fabsf(p0.z); ab[3] += fabsf(p0.w);
        ab[4] += fabsf(p1.x); ab[5] += fabsf(p1.y);
        ab[6] += fabsf(p1.z); ab[7] += fabsf(p1.w);
    }

    // target_spatial: OR over boxes. Segments share columns, differ in row.
    bool ts[8];
    #pragma unroll
    for (int i = 0; i < 8; i++) ts[i] = false;
    #pragma unroll
    for (int o = 0; o < N_OBJ; o++) {
        if (!s_valid[o]) continue;
        const int ys = s_ys[o], ye = s_ye[o];
        const int xs = s_xs[o], xe = s_xe[o];
        const bool rowok0 = (row0 >= ys) && (row0 < ye);
        const bool rowok1 = (row1 >= ys) && (row1 < ye);
        if (rowok0 | rowok1) {
            #pragma unroll
            for (int i = 0; i < 4; i++) {
                const bool colok = (col0 + i >= xs) && (col0 + i < xe);
                ts[i]     |= rowok0 & colok;
                ts[4 + i] |= rowok1 & colok;
            }
        }
    }

    const float inv_c = 1.0f / (float)CC;
    float sp = 0.f;
    unsigned int cnt = 0u;
    #pragma unroll
    for (int i = 0; i < 8; i++) {
        float sa = ab[i] * inv_c;
        float e = sa - (ts[i] ? 1.0f : 0.0f);
        sp = fmaf(e, e, sp);
        cnt += (sa > 0.5f);
    }

    // Block reduction: warp shuffle, then cross-warp via shared
    #pragma unroll
    for (int off = 16; off > 0; off >>= 1) {
        sq  += __shfl_down_sync(0xffffffffu, sq,  off);
        sp  += __shfl_down_sync(0xffffffffu, sp,  off);
        cnt += __shfl_down_sync(0xffffffffu, cnt, off);
    }

    __shared__ float  sh_sq[8], sh_sp[8];
    __shared__ unsigned int sh_cnt[8];
    const int wid = tid >> 5, lid = tid & 31;
    if (lid == 0) { sh_sq[wid] = sq; sh_sp[wid] = sp; sh_cnt[wid] = cnt; }
    __syncthreads();
    if (wid == 0) {
        float  bsq = (lid < 8) ? sh_sq[lid] : 0.f;
        float  bsp = (lid < 8) ? sh_sp[lid] : 0.f;
        unsigned int bcn = (lid < 8) ? sh_cnt[lid] : 0u;
        #pragma unroll
        for (int off = 4; off > 0; off >>= 1) {
            bsq += __shfl_down_sync(0xffffffffu, bsq, off);
            bsp += __shfl_down_sync(0xffffffffu, bsp, off);
            bcn += __shfl_down_sync(0xffffffffu, bcn, off);
        }
        if (lid == 0) {
            atomicAdd(&g_base_sum, (double)bsq);
            atomicAdd(&g_spatial_sum, (double)bsp);
            atomicAdd(&g_counts[b], bcn);
        }
    }

    // ---- last-block finalization (threadFenceReduction pattern) ----
    __shared__ unsigned int s_last;
    if (tid == 0) {
        __threadfence();                       // make my atomics visible
        unsigned int old = atomicAdd(&g_arrive, 1u);
        s_last = (old == (unsigned int)(NBLOCKS - 1)) ? 1u : 0u;
    }
    __syncthreads();

    if (s_last && tid < BB) {
        unsigned int pc_u = *((volatile unsigned int*)&g_counts[tid]);
        float oc = object_counts[tid];
        float d = (float)pc_u - oc;
        float term = d * d;
        #pragma unroll
        for (int off = 16; off > 0; off >>= 1)
            term += __shfl_down_sync(0xffffffffu, term, off);

        g_counts[tid] = 0u;                    // reset for next replay

        if (tid == 0) {
            double bs = *((volatile double*)&g_base_sum);
            double ss = *((volatile double*)&g_spatial_sum);
            double base_loss     = bs / ((double)BB * CC * HW);
            double spatial_loss  = ss / ((double)BB * HW);
            double counting_loss = (double)term / (double)BB;
            out[0] = (float)(base_loss + spatial_loss + 0.5 * counting_loss);
            g_base_sum = 0.0;
            g_spatial_sum = 0.0;
            g_arrive = 0u;
        }
    }
}

extern "C" void kernel_launch(void* const* d_in, const int* in_sizes, int n_in,
                              void* d_out, int out_size)
{
    const float* pred   = (const float*)d_in[0];
    const float* targ   = (const float*)d_in[1];
    const float* layout = (const float*)d_in[2];
    const float* counts = (const float*)d_in[3];
    float* out = (float*)d_out;

    dim3 grid(NBLOCKS_X, BB);   // (32, 32)
    scl_fused_kernel<<<grid, TPB>>>(pred, targ, layout, counts, out);
}

// round 14
// speedup vs baseline: 1.2199x; 1.2199x over previous
#include <cuda_runtime.h>
#include <math.h>

// Problem constants (fixed by reference setup_inputs)
#define BB 32
#define CC 16
#define HH 256
#define WW 256
#define HW (HH * WW)
#define N_OBJ 16
#define TPB 256
#define NBLOCKS_X (HW / (TPB * 4))     // 64
#define NBLOCKS   (NBLOCKS_X * BB)     // 2048

// Global accumulators (zero-initialized at module load; last block resets
// them after consuming, so every graph replay starts from zero).
__device__ double g_base_sum;
__device__ double g_spatial_sum;
__device__ unsigned int g_counts[BB];
__device__ unsigned int g_arrive;

// Single fused kernel: streaming reduction + last-block finalization.
// grid: (64, 32) ; block: 256 ; each thread: 4 consecutive pixels.
// minBlocksPerMultiprocessor=8 pins regs <= 32 -> 8 CTAs/SM, single wave.
__global__ void __launch_bounds__(TPB, 8) scl_fused_kernel(
    const float* __restrict__ pred,
    const float* __restrict__ targ,
    const float* __restrict__ layout,
    const float* __restrict__ object_counts,
    float* __restrict__ out)
{
    const int b = blockIdx.y;
    const int tid = threadIdx.x;

    // Per-batch box bounds in shared memory
    __shared__ int s_xs[N_OBJ], s_xe[N_OBJ], s_ys[N_OBJ], s_ye[N_OBJ];
    __shared__ int s_valid[N_OBJ];
    if (tid < N_OBJ) {
        const float* L = layout + ((size_t)b * N_OBJ + tid) * 4;
        float x = L[0], y = L[1], w = L[2], h = L[3];
        s_valid[tid] = (x > 0.0f) && (y > 0.0f);
        s_xs[tid] = (int)floorf(x * (float)WW);
        s_ys[tid] = (int)floorf(y * (float)HH);
        s_xe[tid] = (int)floorf((x + w) * (float)WW);
        s_ye[tid] = (int)floorf((y + h) * (float)HH);
    }
    __syncthreads();

    // Pixel group: 4 consecutive pixels in one row
    const int pix = (blockIdx.x * TPB + tid) * 4;
    const int row  = pix / WW;
    const int col0 = pix % WW;

    const size_t base = (size_t)b * CC * HW + pix;

    float abs0 = 0.f, abs1 = 0.f, abs2 = 0.f, abs3 = 0.f;
    float sq = 0.f;

    #pragma unroll
    for (int c = 0; c < CC; c++) {
        const float4 p = __ldcs(reinterpret_cast<const float4*>(pred + base + (size_t)c * HW));
        const float4 t = __ldcs(reinterpret_cast<const float4*>(targ + base + (size_t)c * HW));
        float d0 = p.x - t.x, d1 = p.y - t.y, d2 = p.z - t.z, d3 = p.w - t.w;
        sq = fmaf(d0, d0, sq); sq = fmaf(d1, d1, sq);
        sq = fmaf(d2, d2, sq); sq = fmaf(d3, d3, sq);
        abs0 += fabsf(p.x); abs1 += fabsf(p.y);
        abs2 += fabsf(p.z); abs3 += fabsf(p.w);
    }

    // target_spatial: OR over boxes (row test hoisted — all 4 pixels share row)
    bool ts0 = false, ts1 = false, ts2 = false, ts3 = false;
    #pragma unroll
    for (int o = 0; o < N_OBJ; o++) {
        bool rowok = s_valid[o] && (row >= s_ys[o]) && (row < s_ye[o]);
        if (rowok) {
            int xs = s_xs[o], xe = s_xe[o];
            ts0 |= (col0 + 0 >= xs) && (col0 + 0 < xe);
            ts1 |= (col0 + 1 >= xs) && (col0 + 1 < xe);
            ts2 |= (col0 + 2 >= xs) && (col0 + 2 < xe);
            ts3 |= (col0 + 3 >= xs) && (col0 + 3 < xe);
        }
    }

    const float inv_c = 1.0f / (float)CC;
    float sa0 = abs0 * inv_c, sa1 = abs1 * inv_c, sa2 = abs2 * inv_c, sa3 = abs3 * inv_c;

    float e0 = sa0 - (ts0 ? 1.0f : 0.0f);
    float e1 = sa1 - (ts1 ? 1.0f : 0.0f);
    float e2 = sa2 - (ts2 ? 1.0f : 0.0f);
    float e3 = sa3 - (ts3 ? 1.0f : 0.0f);
    float sp = e0 * e0 + e1 * e1 + e2 * e2 + e3 * e3;

    unsigned int cnt = (sa0 > 0.5f) + (sa1 > 0.5f) + (sa2 > 0.5f) + (sa3 > 0.5f);

    // Block reduction: warp shuffle, then cross-warp via shared
    #pragma unroll
    for (int off = 16; off > 0; off >>= 1) {
        sq  += __shfl_down_sync(0xffffffffu, sq,  off);
        sp  += __shfl_down_sync(0xffffffffu, sp,  off);
        cnt += __shfl_down_sync(0xffffffffu, cnt, off);
    }

    __shared__ float  sh_sq[8], sh_sp[8];
    __shared__ unsigned int sh_cnt[8];
    const int wid = tid >> 5, lid = tid & 31;
    if (lid == 0) { sh_sq[wid] = sq; sh_sp[wid] = sp; sh_cnt[wid] = cnt; }
    __syncthreads();
    if (wid == 0) {
        float  bsq = (lid < 8) ? sh_sq[lid] : 0.f;
        float  bsp = (lid < 8) ? sh_sp[lid] : 0.f;
        unsigned int bcn = (lid < 8) ? sh_cnt[lid] : 0u;
        #pragma unroll
        for (int off = 4; off > 0; off >>= 1) {
            bsq += __shfl_down_sync(0xffffffffu, bsq, off);
            bsp += __shfl_down_sync(0xffffffffu, bsp, off);
            bcn += __shfl_down_sync(0xffffffffu, bcn, off);
        }
        if (lid == 0) {
            atomicAdd(&g_base_sum, (double)bsq);
            atomicAdd(&g_spatial_sum, (double)bsp);
            atomicAdd(&g_counts[b], bcn);
        }
    }

    // ---- last-block finalization (threadFenceReduction pattern) ----
    __shared__ unsigned int s_last;
    if (tid == 0) {
        __threadfence();                       // make my atomics visible
        unsigned int old = atomicAdd(&g_arrive, 1u);
        s_last = (old == (unsigned int)(NBLOCKS - 1)) ? 1u : 0u;
    }
    __syncthreads();

    if (s_last && tid < BB) {
        // All other blocks' atomics are visible (they fenced before arriving).
        unsigned int pc_u = *((volatile unsigned int*)&g_counts[tid]);
        float oc = object_counts[tid];
        float d = (float)pc_u - oc;
        float term = d * d;
        #pragma unroll
        for (int off = 16; off > 0; off >>= 1)
            term += __shfl_down_sync(0xffffffffu, term, off);

        g_counts[tid] = 0u;                    // reset for next replay

        if (tid == 0) {
            double bs = *((volatile double*)&g_base_sum);
            double ss = *((volatile double*)&g_spatial_sum);
            double base_loss     = bs / ((double)BB * CC * HW);
            double spatial_loss  = ss / ((double)BB * HW);
            double counting_loss = (double)term / (double)BB;
            out[0] = (float)(base_loss + spatial_loss + 0.5 * counting_loss);
            // reset scalars for next replay
            g_base_sum = 0.0;
            g_spatial_sum = 0.0;
            g_arrive = 0u;
        }
    }
}

extern "C" void kernel_launch(void* const* d_in, const int* in_sizes, int n_in,
                              void* d_out, int out_size)
{
    const float* pred   = (const float*)d_in[0];
    const float* targ   = (const float*)d_in[1];
    const float* layout = (const float*)d_in[2];
    const float* counts = (const float*)d_in[3];
    float* out = (float*)d_out;

    dim3 grid(NBLOCKS_X, BB);   // (64, 32)
    scl_fused_kernel<<<grid, TPB>>>(pred, targ, layout, counts, out);
}

// round 16
// speedup vs baseline: 1.2207x; 1.0007x over previous
#include <cuda_runtime.h>
#include <math.h>

// Problem constants (fixed by reference setup_inputs)
#define BB 32
#define CC 16
#define HH 256
#define WW 256
#define HW (HH * WW)
#define N_OBJ 16
#define TPB 512
#define NBLOCKS_X (HW / (TPB * 4))     // 32
#define NBLOCKS   (NBLOCKS_X * BB)     // 1024
#define NWARPS (TPB / 32)              // 16

// Global accumulators (zero-initialized at module load; last block resets
// them after consuming, so every graph replay starts from zero).
__device__ double g_base_sum;
__device__ double g_spatial_sum;
__device__ unsigned int g_counts[BB];
__device__ unsigned int g_arrive;

// Single fused kernel: streaming reduction + last-block finalization.
// grid: (32, 32) ; block: 512 ; each thread: 4 consecutive pixels.
// minBlocksPerMultiprocessor=4 pins regs <= 32 -> 4 CTAs/SM = 2048 thr/SM.
__global__ void __launch_bounds__(TPB, 4) scl_fused_kernel(
    const float* __restrict__ pred,
    const float* __restrict__ targ,
    const float* __restrict__ layout,
    const float* __restrict__ object_counts,
    float* __restrict__ out)
{
    const int b = blockIdx.y;
    const int tid = threadIdx.x;

    // Per-batch box bounds in shared memory
    __shared__ int s_xs[N_OBJ], s_xe[N_OBJ], s_ys[N_OBJ], s_ye[N_OBJ];
    __shared__ int s_valid[N_OBJ];
    if (tid < N_OBJ) {
        const float* L = layout + ((size_t)b * N_OBJ + tid) * 4;
        float x = L[0], y = L[1], w = L[2], h = L[3];
        s_valid[tid] = (x > 0.0f) && (y > 0.0f);
        s_xs[tid] = (int)floorf(x * (float)WW);
        s_ys[tid] = (int)floorf(y * (float)HH);
        s_xe[tid] = (int)floorf((x + w) * (float)WW);
        s_ye[tid] = (int)floorf((y + h) * (float)HH);
    }
    __syncthreads();

    // Pixel group: 4 consecutive pixels in one row
    const int pix = (blockIdx.x * TPB + tid) * 4;
    const int row  = pix / WW;
    const int col0 = pix % WW;

    const size_t base = (size_t)b * CC * HW + pix;

    float abs0 = 0.f, abs1 = 0.f, abs2 = 0.f, abs3 = 0.f;
    float sq = 0.f;

    #pragma unroll
    for (int c = 0; c < CC; c++) {
        const float4 p = __ldcs(reinterpret_cast<const float4*>(pred + base + (size_t)c * HW));
        const float4 t = __ldcs(reinterpret_cast<const float4*>(targ + base + (size_t)c * HW));
        float d0 = p.x - t.x, d1 = p.y - t.y, d2 = p.z - t.z, d3 = p.w - t.w;
        sq = fmaf(d0, d0, sq); sq = fmaf(d1, d1, sq);
        sq = fmaf(d2, d2, sq); sq = fmaf(d3, d3, sq);
        abs0 += fabsf(p.x); abs1 += fabsf(p.y);
        abs2 += fabsf(p.z); abs3 += fabsf(p.w);
    }

    // target_spatial: OR over boxes (row test hoisted — all 4 pixels share row)
    bool ts0 = false, ts1 = false, ts2 = false, ts3 = false;
    #pragma unroll
    for (int o = 0; o < N_OBJ; o++) {
        bool rowok = s_valid[o] && (row >= s_ys[o]) && (row < s_ye[o]);
        if (rowok) {
            int xs = s_xs[o], xe = s_xe[o];
            ts0 |= (col0 + 0 >= xs) && (col0 + 0 < xe);
            ts1 |= (col0 + 1 >= xs) && (col0 + 1 < xe);
            ts2 |= (col0 + 2 >= xs) && (col0 + 2 < xe);
            ts3 |= (col0 + 3 >= xs) && (col0 + 3 < xe);
        }
    }

    const float inv_c = 1.0f / (float)CC;
    float sa0 = abs0 * inv_c, sa1 = abs1 * inv_c, sa2 = abs2 * inv_c, sa3 = abs3 * inv_c;

    float e0 = sa0 - (ts0 ? 1.0f : 0.0f);
    float e1 = sa1 - (ts1 ? 1.0f : 0.0f);
    float e2 = sa2 - (ts2 ? 1.0f : 0.0f);
    float e3 = sa3 - (ts3 ? 1.0f : 0.0f);
    float sp = e0 * e0 + e1 * e1 + e2 * e2 + e3 * e3;

    unsigned int cnt = (sa0 > 0.5f) + (sa1 > 0.5f) + (sa2 > 0.5f) + (sa3 > 0.5f);

    // Block reduction: warp shuffle, then cross-warp via shared
    #pragma unroll
    for (int off = 16; off > 0; off >>= 1) {
        sq  += __shfl_down_sync(0xffffffffu, sq,  off);
        sp  += __shfl_down_sync(0xffffffffu, sp,  off);
        cnt += __shfl_down_sync(0xffffffffu, cnt, off);
    }

    __shared__ float  sh_sq[NWARPS], sh_sp[NWARPS];
    __shared__ unsigned int sh_cnt[NWARPS];
    const int wid = tid >> 5, lid = tid & 31;
    if (lid == 0) { sh_sq[wid] = sq; sh_sp[wid] = sp; sh_cnt[wid] = cnt; }
    __syncthreads();
    if (wid == 0) {
        float  bsq = (lid < NWARPS) ? sh_sq[lid] : 0.f;
        float  bsp = (lid < NWARPS) ? sh_sp[lid] : 0.f;
        unsigned int bcn = (lid < NWARPS) ? sh_cnt[lid] : 0u;
        #pragma unroll
        for (int off = 8; off > 0; off >>= 1) {
            bsq += __shfl_down_sync(0xffffffffu, bsq, off);
            bsp += __shfl_down_sync(0xffffffffu, bsp, off);
            bcn += __shfl_down_sync(0xffffffffu, bcn, off);
        }
        if (lid == 0) {
            atomicAdd(&g_base_sum, (double)bsq);
            atomicAdd(&g_spatial_sum, (double)bsp);
            atomicAdd(&g_counts[b], bcn);
        }
    }

    // ---- last-block finalization (threadFenceReduction pattern) ----
    __shared__ unsigned int s_last;
    if (tid == 0) {
        __threadfence();                       // make my atomics visible
        unsigned int old = atomicAdd(&g_arrive, 1u);
        s_last = (old == (unsigned int)(NBLOCKS - 1)) ? 1u : 0u;
    }
    __syncthreads();

    if (s_last && tid < BB) {
        // All other blocks' atomics are visible (they fenced before arriving).
        unsigned int pc_u = *((volatile unsigned int*)&g_counts[tid]);
        float oc = object_counts[tid];
        float d = (float)pc_u - oc;
        float term = d * d;
        #pragma unroll
        for (int off = 16; off > 0; off >>= 1)
            term += __shfl_down_sync(0xffffffffu, term, off);

        g_counts[tid] = 0u;                    // reset for next replay

        if (tid == 0) {
            double bs = *((volatile double*)&g_base_sum);
            double ss = *((volatile double*)&g_spatial_sum);
            double base_loss     = bs / ((double)BB * CC * HW);
            double spatial_loss  = ss / ((double)BB * HW);
            double counting_loss = (double)term / (double)BB;
            out[0] = (float)(base_loss + spatial_loss + 0.5 * counting_loss);
            // reset scalars for next replay
            g_base_sum = 0.0;
            g_spatial_sum = 0.0;
            g_arrive = 0u;
        }
    }
}

extern "C" void kernel_launch(void* const* d_in, const int* in_sizes, int n_in,
                              void* d_out, int out_size)
{
    const float* pred   = (const float*)d_in[0];
    const float* targ   = (const float*)d_in[1];
    const float* layout = (const float*)d_in[2];
    const float* counts = (const float*)d_in[3];
    float* out = (float*)d_out;

    dim3 grid(NBLOCKS_X, BB);   // (32, 32)
    scl_fused_kernel<<<grid, TPB>>>(pred, targ, layout, counts, out);
}